// round 12
// baseline (speedup 1.0000x reference)
#include <cuda_runtime.h>
#include <mma.h>
#include <cstdint>

using namespace nvcuda;

#define N_NODES 50000
#define N_PAD   50048
#define N_EDGES 800000
#define HID 64
#define N_CLS 16
#define MAX_DEG 64

// Scratch (device globals — no allocation allowed)
__device__ int   g_cnt[N_NODES];
__device__ int   g_adj[N_NODES * MAX_DEG];
__device__ __align__(16) float g_mean[N_PAD * HID];    // tf32-rounded mean (padded, tail zero)
__device__ __align__(16) float g_xr[N_PAD * HID];      // tf32-rounded x    (padded, tail zero)
__device__ __align__(16) float g_h[N_PAD * HID];
__device__ __align__(16) float g_p[N_PAD * N_CLS];
__device__ __align__(16) float g_pm[N_NODES * N_CLS];
// Pre-rounded tf32 weights
__device__ __align__(16) float g_w1[128 * 64];    // rows 0..63 = W1l, 64..127 = W1r
__device__ __align__(16) float g_w2l[64 * 16];
__device__ __align__(16) float g_w2r[64 * 16];

// ---------------------------------------------------------------------------
// Init: zero counters, round weights + x to tf32, zero pad rows. Idempotent.
// Launched with >= N_PAD*64 threads.
// ---------------------------------------------------------------------------
__global__ void init_k(const float* __restrict__ x,
                       const float* __restrict__ W1l, const float* __restrict__ W1r,
                       const float* __restrict__ W2l, const float* __restrict__ W2r) {
    int i = blockIdx.x * blockDim.x + threadIdx.x;
    if (i < N_NODES) g_cnt[i] = 0;
    if (i < 4096) {
        g_w1[i]        = wmma::__float_to_tf32(W1l[i]);
        g_w1[4096 + i] = wmma::__float_to_tf32(W1r[i]);
    }
    if (i < 1024) {
        g_w2l[i] = wmma::__float_to_tf32(W2l[i]);
        g_w2r[i] = wmma::__float_to_tf32(W2r[i]);
    }
    if (i < N_PAD * HID) {
        int node = i >> 6;
        if (node < N_NODES) {
            g_xr[i] = wmma::__float_to_tf32(x[i]);
        } else {
            g_xr[i]   = 0.f;
            g_mean[i] = 0.f;
        }
    }
}

__global__ void fill_k(const int* __restrict__ ei) {
    int e = blockIdx.x * blockDim.x + threadIdx.x;
    if (e >= N_EDGES) return;
    int s = ei[e];
    int d = ei[N_EDGES + e];
    if ((unsigned)s >= N_NODES || (unsigned)d >= N_NODES) return;
    int pos = atomicAdd(&g_cnt[d], 1);
    if (pos < MAX_DEG) g_adj[d * MAX_DEG + pos] = s;
}

// ---------------------------------------------------------------------------
// Mean gather, split x2: 2*W4 threads per node.
// SEL 0: src = x,   dst = g_mean (tf32-rounded), W4 = 16
// SEL 1: src = g_p, dst = g_pm   (fp32),         W4 = 4
// ---------------------------------------------------------------------------
template<int SEL, int LOG_W4>
__global__ void gather_mean_k(const float4* __restrict__ xin) {
    constexpr int W4 = 1 << LOG_W4;
    const float4* src = (SEL == 0) ? xin : reinterpret_cast<const float4*>(g_p);
    float4* dst = (SEL == 0) ? reinterpret_cast<float4*>(g_mean)
                             : reinterpret_cast<float4*>(g_pm);
    int t = blockIdx.x * blockDim.x + threadIdx.x;
    int node = t >> (LOG_W4 + 1);
    int sub  = t & (2 * W4 - 1);
    int g    = sub >> LOG_W4;
    int f    = sub & (W4 - 1);
    if (node >= N_NODES) return;
    int c = g_cnt[node];
    int cl = min(c, MAX_DEG);
    const int4* row4 = reinterpret_cast<const int4*>(g_adj + (size_t)node * MAX_DEG);
    float4 a0 = make_float4(0.f,0.f,0.f,0.f), a1 = a0;
    int nfull = cl >> 2;
#pragma unroll 2
    for (int j4 = 0; j4 < nfull; j4++) {
        int4 idx = __ldg(row4 + j4);
        int i0 = g ? idx.z : idx.x;
        int i1 = g ? idx.w : idx.y;
        float4 v0 = __ldg(src + (((size_t)i0) << LOG_W4) + f);
        float4 v1 = __ldg(src + (((size_t)i1) << LOG_W4) + f);
        a0.x += v0.x; a0.y += v0.y; a0.z += v0.z; a0.w += v0.w;
        a1.x += v1.x; a1.y += v1.y; a1.z += v1.z; a1.w += v1.w;
    }
    for (int j = nfull * 4 + g; j < cl; j += 2) {
        int s = __ldg(g_adj + (size_t)node * MAX_DEG + j);
        float4 v = __ldg(src + (((size_t)s) << LOG_W4) + f);
        a0.x += v.x; a0.y += v.y; a0.z += v.z; a0.w += v.w;
    }
    float4 r;
    r.x = a0.x + a1.x; r.y = a0.y + a1.y; r.z = a0.z + a1.z; r.w = a0.w + a1.w;
    r.x += __shfl_xor_sync(0xffffffff, r.x, W4);
    r.y += __shfl_xor_sync(0xffffffff, r.y, W4);
    r.z += __shfl_xor_sync(0xffffffff, r.z, W4);
    r.w += __shfl_xor_sync(0xffffffff, r.w, W4);
    if (g == 0) {
        float invd = 1.0f / fmaxf((float)c, 1.0f);
        r.x *= invd; r.y *= invd; r.z *= invd; r.w *= invd;
        if (SEL == 0) {
            r.x = wmma::__float_to_tf32(r.x);
            r.y = wmma::__float_to_tf32(r.y);
            r.z = wmma::__float_to_tf32(r.z);
            r.w = wmma::__float_to_tf32(r.w);
        }
        dst[((size_t)node << LOG_W4) + f] = r;
    }
}

// ---------------------------------------------------------------------------
// Layer 1, fully warp-independent (ZERO block syncs):
//   warp owns 16 rows; h = relu([mean||x] @ g_w1 + b1); p = h @ g_w2l
// A-fragments straight from padded global; B from pre-rounded global (L1).
// ---------------------------------------------------------------------------
__global__ void __launch_bounds__(128)
layer1_k(const float* __restrict__ b1) {
    __shared__ float sH[4][16][68];   // per-warp h patch; 17.4KB
    int tid = threadIdx.x, warp = tid >> 5, lane = tid & 31;
    int row0 = blockIdx.x * 64 + warp * 16;   // this warp's global m-tile origin

    wmma::fragment<wmma::accumulator, 16, 16, 8, float> acc[4];
#pragma unroll
    for (int n = 0; n < 4; n++) wmma::fill_fragment(acc[n], 0.f);

#pragma unroll
    for (int kk = 0; kk < 16; kk++) {
        const float* Asrc = (kk < 8) ? (g_mean + (size_t)row0 * 64 + kk * 8)
                                     : (g_xr   + (size_t)row0 * 64 + (kk - 8) * 8);
        wmma::fragment<wmma::matrix_a, 16, 16, 8, wmma::precision::tf32, wmma::row_major> a;
        wmma::load_matrix_sync(a, Asrc, 64);
#pragma unroll
        for (int n = 0; n < 4; n++) {
            wmma::fragment<wmma::matrix_b, 16, 16, 8, wmma::precision::tf32, wmma::row_major> b;
            wmma::load_matrix_sync(b, g_w1 + (size_t)kk * 8 * 64 + n * 16, 64);
            wmma::mma_sync(acc[n], a, b, acc[n]);
        }
    }

#pragma unroll
    for (int n = 0; n < 4; n++)
        wmma::store_matrix_sync(&sH[warp][0][n * 16], acc[n], 68, wmma::mem_row_major);
    __syncwarp();

    // bias + relu + round; write g_h (guarded)
    for (int i = lane; i < 1024; i += 32) {
        int r = i >> 6, c = i & 63;
        float v = wmma::__float_to_tf32(fmaxf(sH[warp][r][c] + b1[c], 0.f));
        sH[warp][r][c] = v;
        int node = row0 + r;
        if (node < N_NODES) g_h[(size_t)node * 64 + c] = v;
    }
    __syncwarp();

    // p = h @ W2l, direct store to padded g_p
    wmma::fragment<wmma::accumulator, 16, 16, 8, float> acc2;
    wmma::fill_fragment(acc2, 0.f);
#pragma unroll
    for (int kk = 0; kk < 8; kk++) {
        wmma::fragment<wmma::matrix_a, 16, 16, 8, wmma::precision::tf32, wmma::row_major> a2;
        wmma::load_matrix_sync(a2, &sH[warp][0][kk * 8], 68);
        wmma::fragment<wmma::matrix_b, 16, 16, 8, wmma::precision::tf32, wmma::row_major> b2;
        wmma::load_matrix_sync(b2, g_w2l + (size_t)kk * 8 * 16, 16);
        wmma::mma_sync(acc2, a2, b2, acc2);
    }
    wmma::store_matrix_sync(g_p + (size_t)row0 * 16, acc2, 16, wmma::mem_row_major);
}

// ---------------------------------------------------------------------------
// Final, warp-independent: out = g_pm + h @ W2r + b2
// ---------------------------------------------------------------------------
__global__ void __launch_bounds__(128)
final_k(const float* __restrict__ b2, float* __restrict__ out) {
    __shared__ float sO[4][16][16];
    int tid = threadIdx.x, warp = tid >> 5, lane = tid & 31;
    int row0 = blockIdx.x * 64 + warp * 16;

    wmma::fragment<wmma::accumulator, 16, 16, 8, float> acc;
    wmma::fill_fragment(acc, 0.f);
#pragma unroll
    for (int kk = 0; kk < 8; kk++) {
        wmma::fragment<wmma::matrix_a, 16, 16, 8, wmma::precision::tf32, wmma::row_major> a;
        wmma::load_matrix_sync(a, g_h + (size_t)row0 * 64 + kk * 8, 64);
        wmma::fragment<wmma::matrix_b, 16, 16, 8, wmma::precision::tf32, wmma::row_major> b;
        wmma::load_matrix_sync(b, g_w2r + (size_t)kk * 8 * 16, 16);
        wmma::mma_sync(acc, a, b, acc);
    }
    wmma::store_matrix_sync(&sO[warp][0][0], acc, 16, wmma::mem_row_major);
    __syncwarp();

    for (int i = lane; i < 256; i += 32) {
        int r = i >> 4, c = i & 15;
        int node = row0 + r;
        if (node < N_NODES)
            out[(size_t)node * 16 + c] = sO[warp][r][c] + g_pm[(size_t)node * 16 + c] + b2[c];
    }
}

// ---------------------------------------------------------------------------
extern "C" void kernel_launch(void* const* d_in, const int* in_sizes, int n_in,
                              void* d_out, int out_size) {
    const float* x   = (const float*)d_in[0];
    const int*   ei  = (const int*)d_in[1];     // int32 (JAX x64 disabled)
    const float* W1l = (const float*)d_in[2];
    const float* b1  = (const float*)d_in[3];
    const float* W1r = (const float*)d_in[4];
    const float* W2l = (const float*)d_in[5];
    const float* b2  = (const float*)d_in[6];
    const float* W2r = (const float*)d_in[7];
    float* out = (float*)d_out;

    const int NBLK = (N_NODES + 63) / 64;   // 782

    init_k<<<(N_PAD * HID + 255) / 256, 256>>>(x, W1l, W1r, W2l, W2r);
    fill_k<<<(N_EDGES + 255) / 256, 256>>>(ei);
    gather_mean_k<0, 4><<<(N_NODES * 32 + 255) / 256, 256>>>((const float4*)x);
    layer1_k<<<NBLK, 128>>>(b1);
    gather_mean_k<1, 2><<<(N_NODES * 8 + 255) / 256, 256>>>(nullptr);
    final_k<<<NBLK, 128>>>(b2, out);
}

// round 13
// speedup vs baseline: 1.1859x; 1.1859x over previous
#include <cuda_runtime.h>
#include <mma.h>
#include <cuda_fp16.h>
#include <cstdint>

using namespace nvcuda;

#define N_NODES 50000
#define N_PAD   50048
#define N_EDGES 800000
#define HID 64
#define N_CLS 16
#define MAX_DEG 64

// Scratch (device globals — no allocation allowed)
__device__ int    g_cnt[N_NODES];
__device__ int    g_adj[N_NODES * MAX_DEG];
__device__ __align__(16) __half g_xh[N_PAD * HID];     // x as half (padded, tail 0)
__device__ __align__(16) __half g_meanh[N_PAD * HID];  // mean as half (padded, tail 0)
__device__ __align__(16) __half g_h[N_PAD * HID];      // layer-1 output, half
__device__ __align__(16) float  g_p[N_PAD * N_CLS];    // h @ W2_l, fp32
__device__ __align__(16) float  g_pm[N_NODES * N_CLS]; // mean of p, fp32
// Pre-converted half weights
__device__ __align__(16) __half g_w1h[128 * 64];   // rows 0..63 = W1l, 64..127 = W1r
__device__ __align__(16) __half g_w2lh[64 * 16];
__device__ __align__(16) __half g_w2rh[64 * 16];

// ---------------------------------------------------------------------------
// Init: zero counters, weights->half, x->half, zero pad rows. Idempotent.
// ---------------------------------------------------------------------------
__global__ void init_k(const float* __restrict__ x,
                       const float* __restrict__ W1l, const float* __restrict__ W1r,
                       const float* __restrict__ W2l, const float* __restrict__ W2r) {
    int i = blockIdx.x * blockDim.x + threadIdx.x;
    if (i < N_NODES) g_cnt[i] = 0;
    if (i < 4096) {
        g_w1h[i]        = __float2half_rn(W1l[i]);
        g_w1h[4096 + i] = __float2half_rn(W1r[i]);
    }
    if (i < 1024) {
        g_w2lh[i] = __float2half_rn(W2l[i]);
        g_w2rh[i] = __float2half_rn(W2r[i]);
    }
    if (i < N_PAD * HID) {
        int node = i >> 6;
        if (node < N_NODES) {
            g_xh[i] = __float2half_rn(x[i]);
        } else {
            g_xh[i]    = __float2half_rn(0.f);
            g_meanh[i] = __float2half_rn(0.f);
        }
    }
}

__global__ void fill_k(const int* __restrict__ ei) {
    int e = blockIdx.x * blockDim.x + threadIdx.x;
    if (e >= N_EDGES) return;
    int s = ei[e];
    int d = ei[N_EDGES + e];
    if ((unsigned)s >= N_NODES || (unsigned)d >= N_NODES) return;
    int pos = atomicAdd(&g_cnt[d], 1);
    if (pos < MAX_DEG) g_adj[d * MAX_DEG + pos] = s;
}

// ---------------------------------------------------------------------------
// Mean gather over half rows: 16 threads/node (2 slots x 8 uint4-lanes).
// Reads g_xh (8 uint4 per 64-half row), accumulates fp32, writes half mean.
// ---------------------------------------------------------------------------
__global__ void gather_mean_x_k() {
    int t = blockIdx.x * blockDim.x + threadIdx.x;
    int node = t >> 4;
    int sub  = t & 15;
    int g    = sub >> 3;     // neighbor slot 0/1
    int f    = sub & 7;      // uint4 index within row (8 halves each)
    if (node >= N_NODES) return;
    int c = g_cnt[node];
    int cl = min(c, MAX_DEG);
    const int4* row4 = reinterpret_cast<const int4*>(g_adj + (size_t)node * MAX_DEG);
    const uint4* src = reinterpret_cast<const uint4*>(g_xh);

    float2 a[4] = {{0.f,0.f},{0.f,0.f},{0.f,0.f},{0.f,0.f}};
    float2 b[4] = {{0.f,0.f},{0.f,0.f},{0.f,0.f},{0.f,0.f}};
    int nfull = cl >> 2;
#pragma unroll 2
    for (int j4 = 0; j4 < nfull; j4++) {
        int4 idx = __ldg(row4 + j4);
        int i0 = g ? idx.z : idx.x;
        int i1 = g ? idx.w : idx.y;
        uint4 v0 = __ldg(src + ((size_t)i0 << 3) + f);
        uint4 v1 = __ldg(src + ((size_t)i1 << 3) + f);
        const __half2* h0 = reinterpret_cast<const __half2*>(&v0);
        const __half2* h1 = reinterpret_cast<const __half2*>(&v1);
#pragma unroll
        for (int q = 0; q < 4; q++) {
            float2 f0 = __half22float2(h0[q]);
            float2 f1 = __half22float2(h1[q]);
            a[q].x += f0.x; a[q].y += f0.y;
            b[q].x += f1.x; b[q].y += f1.y;
        }
    }
    for (int j = nfull * 4 + g; j < cl; j += 2) {
        int s = __ldg(g_adj + (size_t)node * MAX_DEG + j);
        uint4 v = __ldg(src + ((size_t)s << 3) + f);
        const __half2* h = reinterpret_cast<const __half2*>(&v);
#pragma unroll
        for (int q = 0; q < 4; q++) {
            float2 fv = __half22float2(h[q]);
            a[q].x += fv.x; a[q].y += fv.y;
        }
    }
    float r[8];
#pragma unroll
    for (int q = 0; q < 4; q++) {
        r[q * 2]     = a[q].x + b[q].x;
        r[q * 2 + 1] = a[q].y + b[q].y;
    }
#pragma unroll
    for (int q = 0; q < 8; q++)
        r[q] += __shfl_xor_sync(0xffffffff, r[q], 8);
    if (g == 0) {
        float invd = 1.0f / fmaxf((float)c, 1.0f);
        uint4 o;
        __half2* oh = reinterpret_cast<__half2*>(&o);
#pragma unroll
        for (int q = 0; q < 4; q++)
            oh[q] = __floats2half2_rn(r[q * 2] * invd, r[q * 2 + 1] * invd);
        reinterpret_cast<uint4*>(g_meanh)[((size_t)node << 3) + f] = o;
    }
}

// ---------------------------------------------------------------------------
// p-mean gather (fp32, 16 floats/row): 8 threads/node (2 slots x 4 f4-lanes).
// ---------------------------------------------------------------------------
__global__ void gather_mean_p_k() {
    int t = blockIdx.x * blockDim.x + threadIdx.x;
    int node = t >> 3;
    int sub  = t & 7;
    int g    = sub >> 2;
    int f    = sub & 3;
    if (node >= N_NODES) return;
    int c = g_cnt[node];
    int cl = min(c, MAX_DEG);
    const int4* row4 = reinterpret_cast<const int4*>(g_adj + (size_t)node * MAX_DEG);
    const float4* src = reinterpret_cast<const float4*>(g_p);
    float4 a0 = make_float4(0.f,0.f,0.f,0.f), a1 = a0;
    int nfull = cl >> 2;
#pragma unroll 2
    for (int j4 = 0; j4 < nfull; j4++) {
        int4 idx = __ldg(row4 + j4);
        int i0 = g ? idx.z : idx.x;
        int i1 = g ? idx.w : idx.y;
        float4 v0 = __ldg(src + ((size_t)i0 << 2) + f);
        float4 v1 = __ldg(src + ((size_t)i1 << 2) + f);
        a0.x += v0.x; a0.y += v0.y; a0.z += v0.z; a0.w += v0.w;
        a1.x += v1.x; a1.y += v1.y; a1.z += v1.z; a1.w += v1.w;
    }
    for (int j = nfull * 4 + g; j < cl; j += 2) {
        int s = __ldg(g_adj + (size_t)node * MAX_DEG + j);
        float4 v = __ldg(src + ((size_t)s << 2) + f);
        a0.x += v.x; a0.y += v.y; a0.z += v.z; a0.w += v.w;
    }
    float4 r;
    r.x = a0.x + a1.x; r.y = a0.y + a1.y; r.z = a0.z + a1.z; r.w = a0.w + a1.w;
    r.x += __shfl_xor_sync(0xffffffff, r.x, 4);
    r.y += __shfl_xor_sync(0xffffffff, r.y, 4);
    r.z += __shfl_xor_sync(0xffffffff, r.z, 4);
    r.w += __shfl_xor_sync(0xffffffff, r.w, 4);
    if (g == 0) {
        float invd = 1.0f / fmaxf((float)c, 1.0f);
        r.x *= invd; r.y *= invd; r.z *= invd; r.w *= invd;
        reinterpret_cast<float4*>(g_pm)[((size_t)node << 2) + f] = r;
    }
}

// ---------------------------------------------------------------------------
// Layer 1, warp-independent, fp16 WMMA (m16n16k16):
//   warp owns 16 rows; h = relu([mean||x] @ W1 + b1); p = h @ W2l
// ---------------------------------------------------------------------------
__global__ void __launch_bounds__(128)
layer1_k(const float* __restrict__ b1) {
    __shared__ float  sF[4][16][68];    // raw acc patch per warp  (17.4KB)
    __shared__ __half sHh[4][16][72];   // h half patch per warp   (9.2KB)
    int tid = threadIdx.x, warp = tid >> 5, lane = tid & 31;
    int row0 = blockIdx.x * 64 + warp * 16;

    wmma::fragment<wmma::accumulator, 16, 16, 16, float> acc[4];
#pragma unroll
    for (int n = 0; n < 4; n++) wmma::fill_fragment(acc[n], 0.f);

#pragma unroll
    for (int kk = 0; kk < 8; kk++) {
        const __half* Asrc = (kk < 4) ? (g_meanh + (size_t)row0 * 64 + kk * 16)
                                      : (g_xh    + (size_t)row0 * 64 + (kk - 4) * 16);
        wmma::fragment<wmma::matrix_a, 16, 16, 16, __half, wmma::row_major> a;
        wmma::load_matrix_sync(a, Asrc, 64);
#pragma unroll
        for (int n = 0; n < 4; n++) {
            wmma::fragment<wmma::matrix_b, 16, 16, 16, __half, wmma::row_major> b;
            wmma::load_matrix_sync(b, g_w1h + (size_t)kk * 16 * 64 + n * 16, 64);
            wmma::mma_sync(acc[n], a, b, acc[n]);
        }
    }
#pragma unroll
    for (int n = 0; n < 4; n++)
        wmma::store_matrix_sync(&sF[warp][0][n * 16], acc[n], 68, wmma::mem_row_major);
    __syncwarp();

    // bias + relu -> half; write g_h (guarded)
    for (int i = lane; i < 1024; i += 32) {
        int r = i >> 6, c = i & 63;
        __half hv = __float2half_rn(fmaxf(sF[warp][r][c] + b1[c], 0.f));
        sHh[warp][r][c] = hv;
        int node = row0 + r;
        if (node < N_NODES) g_h[(size_t)node * 64 + c] = hv;
    }
    __syncwarp();

    // p = h @ W2l, direct store to padded g_p (fp32)
    wmma::fragment<wmma::accumulator, 16, 16, 16, float> acc2;
    wmma::fill_fragment(acc2, 0.f);
#pragma unroll
    for (int kk = 0; kk < 4; kk++) {
        wmma::fragment<wmma::matrix_a, 16, 16, 16, __half, wmma::row_major> a2;
        wmma::load_matrix_sync(a2, &sHh[warp][0][kk * 16], 72);
        wmma::fragment<wmma::matrix_b, 16, 16, 16, __half, wmma::row_major> b2;
        wmma::load_matrix_sync(b2, g_w2lh + (size_t)kk * 16 * 16, 16);
        wmma::mma_sync(acc2, a2, b2, acc2);
    }
    wmma::store_matrix_sync(g_p + (size_t)row0 * 16, acc2, 16, wmma::mem_row_major);
}

// ---------------------------------------------------------------------------
// Final, warp-independent: out = g_pm + h @ W2r + b2
// ---------------------------------------------------------------------------
__global__ void __launch_bounds__(128)
final_k(const float* __restrict__ b2, float* __restrict__ out) {
    __shared__ float sO[4][16][16];
    int tid = threadIdx.x, warp = tid >> 5, lane = tid & 31;
    int row0 = blockIdx.x * 64 + warp * 16;

    wmma::fragment<wmma::accumulator, 16, 16, 16, float> acc;
    wmma::fill_fragment(acc, 0.f);
#pragma unroll
    for (int kk = 0; kk < 4; kk++) {
        wmma::fragment<wmma::matrix_a, 16, 16, 16, __half, wmma::row_major> a;
        wmma::load_matrix_sync(a, g_h + (size_t)row0 * 64 + kk * 16, 64);
        wmma::fragment<wmma::matrix_b, 16, 16, 16, __half, wmma::row_major> b;
        wmma::load_matrix_sync(b, g_w2rh + (size_t)kk * 16 * 16, 16);
        wmma::mma_sync(acc, a, b, acc);
    }
    wmma::store_matrix_sync(&sO[warp][0][0], acc, 16, wmma::mem_row_major);
    __syncwarp();

    for (int i = lane; i < 256; i += 32) {
        int r = i >> 4, c = i & 15;
        int node = row0 + r;
        if (node < N_NODES)
            out[(size_t)node * 16 + c] = sO[warp][r][c] + g_pm[(size_t)node * 16 + c] + b2[c];
    }
}

// ---------------------------------------------------------------------------
extern "C" void kernel_launch(void* const* d_in, const int* in_sizes, int n_in,
                              void* d_out, int out_size) {
    const float* x   = (const float*)d_in[0];
    const int*   ei  = (const int*)d_in[1];     // int32 (JAX x64 disabled)
    const float* W1l = (const float*)d_in[2];
    const float* b1  = (const float*)d_in[3];
    const float* W1r = (const float*)d_in[4];
    const float* W2l = (const float*)d_in[5];
    const float* b2  = (const float*)d_in[6];
    const float* W2r = (const float*)d_in[7];
    float* out = (float*)d_out;

    const int NBLK = (N_NODES + 63) / 64;   // 782

    init_k<<<(N_PAD * HID + 255) / 256, 256>>>(x, W1l, W1r, W2l, W2r);
    fill_k<<<(N_EDGES + 255) / 256, 256>>>(ei);
    gather_mean_x_k<<<(N_NODES * 16 + 255) / 256, 256>>>();
    layer1_k<<<NBLK, 128>>>(b1);
    gather_mean_p_k<<<(N_NODES * 8 + 255) / 256, 256>>>();
    final_k<<<NBLK, 128>>>(b2, out);
}